// round 4
// baseline (speedup 1.0000x reference)
#include <cuda_runtime.h>

// x: (128, 32, 2, 64, 64) fp32 -> 4096 tiles of (2, 64, 64).
// plaq[i][j] = t0[i][j] + t1[(i+1)%64][j] - t0[i][(j+1)%64] - t1[i][j]
// out[tile] = mean(cos(plaq))
//
// One tile per WARP, zero smem, zero __syncthreads. Each warp loops over its
// tile in 32 steps (one float4 group per lane per step), unrolled x4 so 12
// LDG.128 are in flight per lane continuously for the warp's entire life.
// j+1 roll in-register: a warp step covers 2 rows of 16 lanes; neighbor lane
// = (l&16)|((l+1)&15) (handles j=63->0 wrap). Row roll i+1 is a second t1
// read that hits L1. Reduction is pure warp shuffles; lane 0 stores.

#define WARPS_PER_CTA 4
#define THREADS (WARPS_PER_CTA * 32)

__global__ __launch_bounds__(THREADS) void plaq_trace_warp_kernel(
    const float4* __restrict__ x4, float* __restrict__ out)
{
    const int lane = threadIdx.x & 31;
    const int wt   = blockIdx.x * WARPS_PER_CTA + (threadIdx.x >> 5); // tile id

    const float4* __restrict__ t0 = x4 + (size_t)wt * 2048; // 1024 float4 each
    const float4* __restrict__ t1 = t0 + 1024;

    const int src = (lane & 16) | ((lane + 1) & 15); // right-neighbor lane

    float acc0 = 0.0f, acc1 = 0.0f, acc2 = 0.0f, acc3 = 0.0f;

    // 32 steps; unroll 4 -> 12 independent LDG.128 per lane per body.
    #pragma unroll 1
    for (int m = 0; m < 32; m += 4) {
        float4 A0[4], A1[4], B1[4];
        #pragma unroll
        for (int u = 0; u < 4; u++) {
            const int g  = (m + u) * 32 + lane;     // float4 group 0..1023
            const int i  = g >> 4;                  // row
            const int jg = g & 15;                  // float4 col
            const int g1 = (((i + 1) & 63) << 4) | jg;
            A0[u] = t0[g];
            A1[u] = t1[g];
            B1[u] = t1[g1];
        }
        #pragma unroll
        for (int u = 0; u < 4; u++) {
            const float nx = __shfl_sync(0xFFFFFFFFu, A0[u].x, src);
            acc0 += __cosf(A0[u].x + B1[u].x - A0[u].y - A1[u].x);
            acc1 += __cosf(A0[u].y + B1[u].y - A0[u].z - A1[u].y);
            acc2 += __cosf(A0[u].z + B1[u].z - A0[u].w - A1[u].z);
            acc3 += __cosf(A0[u].w + B1[u].w - nx      - A1[u].w);
        }
    }

    float sum = (acc0 + acc1) + (acc2 + acc3);
    #pragma unroll
    for (int off = 16; off > 0; off >>= 1)
        sum += __shfl_xor_sync(0xFFFFFFFFu, sum, off);

    if (lane == 0) out[wt] = sum * (1.0f / 4096.0f);
}

extern "C" void kernel_launch(void* const* d_in, const int* in_sizes, int n_in,
                              void* d_out, int out_size)
{
    const float4* x4 = (const float4*)d_in[0];
    float* out = (float*)d_out;
    // 4096 tiles / 4 warps per CTA
    plaq_trace_warp_kernel<<<1024, THREADS>>>(x4, out);
}

// round 5
// speedup vs baseline: 1.2043x; 1.2043x over previous
#include <cuda_runtime.h>

// x: (128, 32, 2, 64, 64) fp32 -> 4096 tiles of (2, 64, 64).
// plaq[i][j] = t0[i][j] + t1[(i+1)%64][j] - t0[i][(j+1)%64] - t1[i][j]
// out[tile] = mean(cos(plaq))
//
// Single-wave persistent version of the R3 register kernel: 1024 CTAs x 256
// threads, launch_bounds(256,7) -> <=36 regs -> 7 CTAs/SM -> every CTA
// resident simultaneously (152 SMs). Each CTA processes exactly 4 tiles
// (zero remainder), eliminating wave transitions and tail quantization.
// Per tile: 12 independent LDG.128 per thread, j+1 roll in-register
// (neighbor lane (l&16)|((l+1)&15)), i+1 roll = second t1 read (L1 hit),
// warp-shuffle + smem block reduction.

#define THREADS 256
#define GRID_CTAS 1024
#define ROUNDS 4          // 4096 tiles / 1024 CTAs

__global__ __launch_bounds__(THREADS, 7) void plaq_trace_persist_kernel(
    const float4* __restrict__ x4, float* __restrict__ out)
{
    const int tid  = threadIdx.x;
    const int lane = tid & 31;
    const int wid  = tid >> 5;
    const int src  = (lane & 16) | ((lane + 1) & 15);  // right neighbor lane

    __shared__ float warp_sums[THREADS / 32];

    #pragma unroll 1
    for (int r = 0; r < ROUNDS; r++) {
        const int t = blockIdx.x + r * GRID_CTAS;
        const float4* __restrict__ t0 = x4 + (size_t)t * 2048;
        const float4* __restrict__ t1 = t0 + 1024;

        float4 A0[4], A1[4], B1[4];
        #pragma unroll
        for (int k = 0; k < 4; k++) {
            const int g  = tid + k * THREADS;     // float4 group 0..1023
            const int i  = g >> 4;                // row
            const int jg = g & 15;                // float4 col
            const int g1 = (((i + 1) & 63) << 4) | jg;
            A0[k] = t0[g];
            A1[k] = t1[g];
            B1[k] = t1[g1];
        }

        float sum = 0.0f;
        #pragma unroll
        for (int k = 0; k < 4; k++) {
            const float nx = __shfl_sync(0xFFFFFFFFu, A0[k].x, src);
            sum += __cosf(A0[k].x + B1[k].x - A0[k].y - A1[k].x);
            sum += __cosf(A0[k].y + B1[k].y - A0[k].z - A1[k].y);
            sum += __cosf(A0[k].z + B1[k].z - A0[k].w - A1[k].z);
            sum += __cosf(A0[k].w + B1[k].w - nx      - A1[k].w);
        }

        #pragma unroll
        for (int off = 16; off > 0; off >>= 1)
            sum += __shfl_xor_sync(0xFFFFFFFFu, sum, off);

        if (lane == 0) warp_sums[wid] = sum;
        __syncthreads();

        if (wid == 0) {
            float s = (lane < (THREADS / 32)) ? warp_sums[lane] : 0.0f;
            #pragma unroll
            for (int off = 4; off > 0; off >>= 1)
                s += __shfl_xor_sync(0xFFFFFFFFu, s, off);
            if (lane == 0) out[t] = s * (1.0f / 4096.0f);
        }
        __syncthreads();   // warp_sums reuse guard for next round
    }
}

extern "C" void kernel_launch(void* const* d_in, const int* in_sizes, int n_in,
                              void* d_out, int out_size)
{
    const float4* x4 = (const float4*)d_in[0];
    float* out = (float*)d_out;
    plaq_trace_persist_kernel<<<GRID_CTAS, THREADS>>>(x4, out);
}